// round 16
// baseline (speedup 1.0000x reference)
#include <cuda_runtime.h>
#include <cuda_bf16.h>
#include <cstdint>

#define T_N 4096
#define B_N 8
#define NL  8
#define NQC 40               // conv chunks: 36 x-parts + 4 packed ctx (240 slots)
#define NQR 12               // rs chunks
#define STG_B 32768          // per stage: 16KB A + 16KB B
#define GEMM_SMEM 98304      // 3 stages, 2 CTAs/SM
#define NTT 32               // t-tiles per batch (4096/128)
#define ITEMS_PER_LAYER 2048 // 1024 conv + 1024 rs
#define TOTAL_ITEMS (NL * ITEMS_PER_LAYER)
#define GRID_P 296           // persistent grid: 148 SMs x 2 CTAs (all resident)

// ---------------- device scratch ----------------
__device__ __align__(16) float         g_x [B_N*T_N*256];
__device__ __align__(16) __nv_bfloat16 g_xh[B_N*T_N*256];
__device__ __align__(16) __nv_bfloat16 g_xl[B_N*T_N*256];
__device__ __align__(16) __nv_bfloat16 g_ah[B_N*T_N*256];
__device__ __align__(16) __nv_bfloat16 g_al[B_N*T_N*256];
__device__ __align__(16) float         g_oa[B_N*T_N*256];
__device__ __align__(16) __nv_bfloat16 g_ch[B_N*T_N*80];
__device__ __align__(16) __nv_bfloat16 g_cl[B_N*T_N*80];
__device__ __align__(16) __nv_bfloat16 g_wc[(size_t)NL*NQC*32768];
__device__ __align__(16) __nv_bfloat16 g_wr[(size_t)NL*NQR*32768];

// persistent-scheduler state (zeroed every launch)
__device__ int g_qhead;
__device__ int g_cdone[NL][B_N * NTT];
__device__ int g_rdone[NL][B_N * NTT];

__constant__ int DILC[NL] = {1, 2, 4, 8, 16, 32, 64, 128};

// ---------------- helpers ----------------
__device__ __forceinline__ uint32_t smem_u32(const void* p) {
    uint32_t a;
    asm("{ .reg .u64 t; cvta.to.shared.u64 t, %1; cvt.u32.u64 %0, t; }" : "=r"(a) : "l"(p));
    return a;
}
__device__ __forceinline__ uint32_t swz(uint32_t x) { return x ^ ((x >> 3) & 0x70); }
__device__ __forceinline__ int ld_cg(const int* p) {
    int v; asm volatile("ld.global.cg.b32 %0, [%1];" : "=r"(v) : "l"(p)); return v;
}

#define CP16(dst, src, sz) \
    asm volatile("cp.async.cg.shared.global [%0], [%1], 16, %2;" \
        :: "r"(dst), "l"(src), "r"(sz) : "memory")
#define CPCOMMIT() asm volatile("cp.async.commit_group;" ::: "memory")
#define CPWAIT1()  asm volatile("cp.async.wait_group 1;" ::: "memory")
#define CPWAIT0()  asm volatile("cp.async.wait_group 0;" ::: "memory")

__device__ __forceinline__ void ldmx4(uint32_t* r, uint32_t a) {
    asm volatile("ldmatrix.sync.aligned.m8n8.x4.shared.b16 {%0,%1,%2,%3}, [%4];"
        : "=r"(r[0]), "=r"(r[1]), "=r"(r[2]), "=r"(r[3]) : "r"(a));
}
__device__ __forceinline__ void mma16816(float* c, const uint32_t* a, const uint32_t* b) {
    asm volatile("mma.sync.aligned.m16n8k16.row.col.f32.bf16.bf16.f32 "
        "{%0,%1,%2,%3}, {%4,%5,%6,%7}, {%8,%9}, {%0,%1,%2,%3};"
        : "+f"(c[0]), "+f"(c[1]), "+f"(c[2]), "+f"(c[3])
        : "r"(a[0]), "r"(a[1]), "r"(a[2]), "r"(a[3]), "r"(b[0]), "r"(b[1]));
}
__device__ __forceinline__ float sigf(float x) { return 1.f / (1.f + __expf(-x)); }

// ---------------- init counters ----------------
__global__ void zero_sync() {
    int i = blockIdx.x * 256 + threadIdx.x;
    if (i == 0) g_qhead = 0;
    if (i < NL * B_N * NTT) {
        ((int*)g_cdone)[i] = 0;
        ((int*)g_rdone)[i] = 0;
    }
}

// ---------------- merged weight-image prep (R10 layout) ----------------
__global__ void prep_all(const float* __restrict__ in_w,
                         const float* __restrict__ cond_w,
                         const float* __restrict__ rs_w) {
    int idx = blockIdx.x * 256 + threadIdx.x;
    const int NC = NL * NQC * 32768;
    if (idx < NC) {
        int li = idx / (NQC * 32768);
        int r  = idx % (NQC * 32768);
        int q = r >> 15, rr = r & 32767;
        int ng = rr >> 6, k = rr & 63;
        int jt = ng >> 7, nq = ng & 127;
        int o = jt * 64 + (nq >> 1), s = nq & 1;
        int och = o + s * 256;
        float w; int p;
        if (q < 36) {
            int pp = q >> 2; p = pp % 3;
            int tap = pp / 3, c = (q & 3) * 64 + k;
            w = in_w[((size_t)(li * 512 + och) * 256 + c) * 3 + tap];
        } else {
            int sidx = (q - 36) * 64 + k;
            if (sidx < 80)       { w = cond_w[(size_t)(li * 512 + och) * 80 + sidx];        p = 0; }
            else if (sidx < 160) { w = cond_w[(size_t)(li * 512 + och) * 80 + sidx - 80];   p = 0; }
            else if (sidx < 240) { w = cond_w[(size_t)(li * 512 + och) * 80 + sidx - 160];  p = 2; }
            else                 { w = 0.f; p = 0; }
        }
        __nv_bfloat16 h = __float2bfloat16(w);
        if (p == 2) h = __float2bfloat16(w - __bfloat162float(h));
        g_wc[(size_t)(li * NQC + q) * 32768 + jt * 8192 + (swz((uint32_t)nq * 128 + k * 2) >> 1)] = h;
    } else {
        idx -= NC;
        if (idx >= NL * NQR * 32768) return;
        int li = idx / (NQR * 32768);
        int r  = idx % (NQR * 32768);
        int q = r >> 15, rr = r & 32767;
        int ng = rr >> 6, k = rr & 63;
        int jt = ng >> 7, nq = ng & 127;
        int o = jt * 64 + (nq >> 1), s = nq & 1;
        int och = o + s * 256;
        int p = q >> 2, c = (q & 3) * 64 + k;
        float w = rs_w[(size_t)(li * 512 + och) * 256 + c];
        __nv_bfloat16 h = __float2bfloat16(w);
        if (p == 2) h = __float2bfloat16(w - __bfloat162float(h));
        g_wr[(size_t)(li * NQR + q) * 32768 + jt * 8192 + (swz((uint32_t)nq * 128 + k * 2) >> 1)] = h;
    }
}

// ---------------- context transpose+split ----------------
__global__ void ctx_prep(const float* __restrict__ ctx) {
    __shared__ float tile[80][33];
    int b = blockIdx.y, t0 = blockIdx.x * 32, tid = threadIdx.x;
    int i = tid & 31, m0 = tid >> 5;
    for (int mm = m0; mm < 80; mm += 8)
        tile[mm][i] = ctx[((size_t)b * 80 + mm) * T_N + t0 + i];
    __syncthreads();
    int tt = tid >> 3, sg = tid & 7;
    size_t rb = ((size_t)b * T_N + t0 + tt) * 80;
    for (int e = 0; e < 10; e++) {
        int m = sg * 10 + e;
        float v = tile[m][tt];
        __nv_bfloat16 h = __float2bfloat16(v);
        g_ch[rb + m] = h;
        g_cl[rb + m] = __float2bfloat16(v - __bfloat162float(h));
    }
}

// ---------------- start conv ----------------
__global__ void start_k(const float* __restrict__ f, const float* __restrict__ sw,
                        const float* __restrict__ sb) {
    __shared__ float ft[4][128];
    int t0 = blockIdx.x * 128, b = blockIdx.y, c = threadIdx.x;
    for (int e = 0; e < 2; e++) {
        int idx = e * 256 + c;
        ft[idx >> 7][idx & 127] = f[((size_t)b * 8 + (idx >> 7)) * T_N + t0 + (idx & 127)];
    }
    float w0 = sw[c * 4], w1 = sw[c * 4 + 1], w2 = sw[c * 4 + 2], w3 = sw[c * 4 + 3];
    float bb = sb[c];
    __syncthreads();
    for (int t = 0; t < 128; t++) {
        float v = fmaf(ft[3][t], w3, fmaf(ft[2][t], w2, fmaf(ft[1][t], w1, fmaf(ft[0][t], w0, bb))));
        size_t o = ((size_t)b * T_N + t0 + t) * 256 + c;
        g_x[o] = v; g_oa[o] = 0.f;
        __nv_bfloat16 h = __float2bfloat16(v);
        g_xh[o] = h;
        g_xl[o] = __float2bfloat16(v - __bfloat162float(h));
    }
}

// ---------------- conv body (R10 conv_k, separate reg allocation) ----------------
__device__ __noinline__ void conv_body(char* sm, uint32_t sb, int li, int d,
                                       int b, int t0, int jt,
                                       const float* __restrict__ ib_,
                                       const float* __restrict__ cb_) {
    int tid = threadIdx.x, wid = tid >> 5, lane = tid & 31;

    int row0 = tid >> 3, seg = tid & 7;
    uint32_t adst0  = (uint32_t)row0 * 128 + (((uint32_t)seg * 16) ^ (((uint32_t)row0 & 7) << 4));
    uint32_t abase0 = ((uint32_t)(b * T_N + t0 + row0)) * 512 + (uint32_t)seg * 16;
    uint32_t crow0  = ((uint32_t)(b * T_N + t0 + row0)) * 160;

    auto stageA = [&](int q, int st) {
        uint32_t ad = sb + st * STG_B + adst0;
        if (q < 36) {
            int pp = q >> 2, p = pp % 3, tap = pp / 3, c0 = (q & 3) * 64;
            const char* bp = (const char*)((p == 1) ? g_xl : g_xh);
            int tsh = (tap - 1) * d;
            const char* base = bp + abase0 + (long long)tsh * 512 + c0 * 2;
#pragma unroll
            for (int e = 0; e < 4; e++) {
                int t = t0 + row0 + 32 * e + tsh;
                int sz = (t >= 0 && t < T_N) ? 16 : 0;
                const char* src = sz ? (base + e * 16384) : bp;
                CP16(ad + e * 4096, src, sz);
            }
        } else {
            int s0 = (q - 36) * 64 + seg * 8;
            const char* base; int sz = 16;
            if (s0 < 80)       base = (const char*)g_ch + crow0 + s0 * 2;
            else if (s0 < 160) base = (const char*)g_cl + crow0 + (s0 - 80) * 2;
            else if (s0 < 240) base = (const char*)g_ch + crow0 + (s0 - 160) * 2;
            else             { base = (const char*)g_ch; sz = 0; }
#pragma unroll
            for (int e = 0; e < 4; e++)
                CP16(ad + e * 4096, base + (sz ? e * 5120 : 0), sz);
        }
    };
    auto stageB = [&](int q, int st) {
        const char* bsrc = (const char*)(g_wc + (size_t)(li * NQC + q) * 32768 + jt * 8192) + tid * 16;
        uint32_t bd = sb + st * STG_B + 16384 + tid * 16;
#pragma unroll
        for (int e = 0; e < 4; e++)
            CP16(bd + e * 4096, bsrc + e * 4096, 16);
    };

    float c[2][8][4];
#pragma unroll
    for (int i = 0; i < 2; i++)
#pragma unroll
        for (int j = 0; j < 8; j++)
#pragma unroll
            for (int k = 0; k < 4; k++) c[i][j][k] = 0.f;

    int mb = (wid & 3) * 32, nb = (wid >> 2) * 64;
    int rA = lane & 15, cA = (lane >> 4) * 16;
    int rB = ((lane >> 4) & 1) * 8 + (lane & 7), cB = ((lane >> 3) & 1) * 16;

    uint32_t aRow = (uint32_t)(mb + rA) * 128;
    uint32_t bRow = (uint32_t)(nb + rB) * 128;
    uint32_t axr = ((uint32_t)rA & 7) << 4;
    uint32_t bxr = ((uint32_t)rB & 7) << 4;
    uint32_t kxA[4], kxB[4];
#pragma unroll
    for (int ks = 0; ks < 4; ks++) {
        kxA[ks] = ((uint32_t)(ks * 32 + cA)) ^ axr;
        kxB[ks] = ((uint32_t)(ks * 32 + cB)) ^ bxr;
    }

    stageA(0, 0); stageB(0, 0); CPCOMMIT();
    stageA(1, 1); stageB(1, 1); CPCOMMIT();

    for (int q = 0; q < NQC; q++) {
        int st = q % 3;
        if (q == NQC - 1) CPWAIT0(); else CPWAIT1();
        __syncthreads();
        if (q + 2 < NQC) {
            int st2 = (q + 2) % 3;
            stageA(q + 2, st2); stageB(q + 2, st2); CPCOMMIT();
        }
        uint32_t aB = sb + st * STG_B, bB = aB + 16384;
        uint32_t aA0 = aB + aRow, aA1 = aA0 + 2048;
        uint32_t bBr = bB + bRow;

        uint32_t af[2][2][4], bf[2][4];
        ldmx4(af[0][0], aA0 + kxA[0]);
        ldmx4(af[0][1], aA1 + kxA[0]);
        ldmx4(bf[0], bBr + kxB[0]);
#pragma unroll
        for (int ks = 0; ks < 4; ks++) {
            int cs = ks & 1, ns = cs ^ 1;
            if (ks < 3) {
                ldmx4(af[ns][0], aA0 + kxA[ks + 1]);
                ldmx4(af[ns][1], aA1 + kxA[ks + 1]);
            }
#pragma unroll
            for (int nj = 0; nj < 4; nj++) {
                int cb2 = nj & 1, nb2 = cb2 ^ 1;
                if (nj < 3)      ldmx4(bf[nb2], bBr + (nj + 1) * 2048 + kxB[ks]);
                else if (ks < 3) ldmx4(bf[nb2], bBr + kxB[ks + 1]);
                mma16816(c[0][nj * 2],     af[cs][0], &bf[cb2][0]);
                mma16816(c[0][nj * 2 + 1], af[cs][0], &bf[cb2][2]);
                mma16816(c[1][nj * 2],     af[cs][1], &bf[cb2][0]);
                mma16816(c[1][nj * 2 + 1], af[cs][1], &bf[cb2][2]);
            }
        }
    }
    __syncthreads();

    __nv_bfloat16* shh = (__nv_bfloat16*)sm;
    __nv_bfloat16* sll = (__nv_bfloat16*)(sm + 20480);
    const float* ib = ib_ + li * 512;
    const float* cb = cb_ + li * 512;
    int qrow = lane >> 2, qcol = lane & 3;
#pragma unroll
    for (int nt = 0; nt < 8; nt++) {
        int ol = (nb >> 1) + nt * 4 + qcol;
        int o = jt * 64 + ol;
        float b1 = ib[o] + cb[o];
        float b2 = ib[o + 256] + cb[o + 256];
#pragma unroll
        for (int mi = 0; mi < 2; mi++) {
            int tl = mb + mi * 16 + qrow;
            float a0 = tanhf(c[mi][nt][0] + b1) * sigf(c[mi][nt][1] + b2);
            float a1 = tanhf(c[mi][nt][2] + b1) * sigf(c[mi][nt][3] + b2);
            __nv_bfloat16 h0 = __float2bfloat16(a0);
            __nv_bfloat16 h1 = __float2bfloat16(a1);
            shh[tl * 72 + ol] = h0;
            sll[tl * 72 + ol] = __float2bfloat16(a0 - __bfloat162float(h0));
            shh[(tl + 8) * 72 + ol] = h1;
            sll[(tl + 8) * 72 + ol] = __float2bfloat16(a1 - __bfloat162float(h1));
        }
    }
    __syncthreads();
#pragma unroll
    for (int e = 0; e < 4; e++) {
        int idx = e * 256 + tid;
        int row = idx >> 3, sg = idx & 7;
        size_t go = (size_t)(b * T_N + t0 + row) * 256 + jt * 64;
        ((uint4*)(g_ah + go))[sg] = ((const uint4*)shh)[row * 9 + sg];
        ((uint4*)(g_al + go))[sg] = ((const uint4*)sll)[row * 9 + sg];
    }
    __syncthreads();
}

// ---------------- rs body (R10 rs_k, separate reg allocation) ----------------
__device__ __noinline__ void rs_body(char* sm, uint32_t sb, int li,
                                     int b, int t0, int jt, int last,
                                     const float* __restrict__ rb_) {
    int tid = threadIdx.x, wid = tid >> 5, lane = tid & 31;

    int row0 = tid >> 3, seg = tid & 7;
    uint32_t adst0  = (uint32_t)row0 * 128 + (((uint32_t)seg * 16) ^ (((uint32_t)row0 & 7) << 4));
    uint32_t abase0 = ((uint32_t)(b * T_N + t0 + row0)) * 512 + (uint32_t)seg * 16;

    auto stageA = [&](int q, int st) {
        int p = q >> 2, c0 = (q & 3) * 64;
        const char* base = (const char*)((p == 1) ? g_al : g_ah) + abase0 + c0 * 2;
        uint32_t ad = sb + st * STG_B + adst0;
#pragma unroll
        for (int e = 0; e < 4; e++)
            CP16(ad + e * 4096, base + e * 16384, 16);
    };
    auto stageB = [&](int q, int st) {
        const char* bsrc = (const char*)(g_wr + (size_t)(li * NQR + q) * 32768 + jt * 8192) + tid * 16;
        uint32_t bd = sb + st * STG_B + 16384 + tid * 16;
#pragma unroll
        for (int e = 0; e < 4; e++)
            CP16(bd + e * 4096, bsrc + e * 4096, 16);
    };

    float c[2][8][4];
#pragma unroll
    for (int i = 0; i < 2; i++)
#pragma unroll
        for (int j = 0; j < 8; j++)
#pragma unroll
            for (int k = 0; k < 4; k++) c[i][j][k] = 0.f;

    int mb = (wid & 3) * 32, nb = (wid >> 2) * 64;
    int rA = lane & 15, cA = (lane >> 4) * 16;
    int rB = ((lane >> 4) & 1) * 8 + (lane & 7), cB = ((lane >> 3) & 1) * 16;

    uint32_t aRow = (uint32_t)(mb + rA) * 128;
    uint32_t bRow = (uint32_t)(nb + rB) * 128;
    uint32_t axr = ((uint32_t)rA & 7) << 4;
    uint32_t bxr = ((uint32_t)rB & 7) << 4;
    uint32_t kxA[4], kxB[4];
#pragma unroll
    for (int ks = 0; ks < 4; ks++) {
        kxA[ks] = ((uint32_t)(ks * 32 + cA)) ^ axr;
        kxB[ks] = ((uint32_t)(ks * 32 + cB)) ^ bxr;
    }

    stageA(0, 0); stageB(0, 0); CPCOMMIT();
    stageA(1, 1); stageB(1, 1); CPCOMMIT();

    for (int q = 0; q < NQR; q++) {
        int st = q % 3;
        if (q == NQR - 1) CPWAIT0(); else CPWAIT1();
        __syncthreads();
        if (q + 2 < NQR) {
            int st2 = (q + 2) % 3;
            stageA(q + 2, st2); stageB(q + 2, st2); CPCOMMIT();
        }
        uint32_t aB = sb + st * STG_B, bB = aB + 16384;
        uint32_t aA0 = aB + aRow, aA1 = aA0 + 2048;
        uint32_t bBr = bB + bRow;

        uint32_t af[2][2][4], bf[2][4];
        ldmx4(af[0][0], aA0 + kxA[0]);
        ldmx4(af[0][1], aA1 + kxA[0]);
        ldmx4(bf[0], bBr + kxB[0]);
#pragma unroll
        for (int ks = 0; ks < 4; ks++) {
            int cs = ks & 1, ns = cs ^ 1;
            if (ks < 3) {
                ldmx4(af[ns][0], aA0 + kxA[ks + 1]);
                ldmx4(af[ns][1], aA1 + kxA[ks + 1]);
            }
#pragma unroll
            for (int nj = 0; nj < 4; nj++) {
                int cb2 = nj & 1, nb2 = cb2 ^ 1;
                if (nj < 3)      ldmx4(bf[nb2], bBr + (nj + 1) * 2048 + kxB[ks]);
                else if (ks < 3) ldmx4(bf[nb2], bBr + kxB[ks + 1]);
                mma16816(c[0][nj * 2],     af[cs][0], &bf[cb2][0]);
                mma16816(c[0][nj * 2 + 1], af[cs][0], &bf[cb2][2]);
                mma16816(c[1][nj * 2],     af[cs][1], &bf[cb2][0]);
                mma16816(c[1][nj * 2 + 1], af[cs][1], &bf[cb2][2]);
            }
        }
    }
    __syncthreads();

    float* sr = (float*)sm;
    float* ss = (float*)(sm + 34816);
    int qrow = lane >> 2, qcol = lane & 3;
#pragma unroll
    for (int nt = 0; nt < 8; nt++) {
        int ol = (nb >> 1) + nt * 4 + qcol;
#pragma unroll
        for (int mi = 0; mi < 2; mi++) {
            int tl = mb + mi * 16 + qrow;
            sr[tl * 68 + ol] = c[mi][nt][0];
            ss[tl * 68 + ol] = c[mi][nt][1];
            sr[(tl + 8) * 68 + ol] = c[mi][nt][2];
            ss[(tl + 8) * 68 + ol] = c[mi][nt][3];
        }
    }
    __syncthreads();
    const float* rb = rb_ + li * 512;
#pragma unroll
    for (int e = 0; e < 8; e++) {
        int idx = e * 256 + tid;
        int row = idx >> 4, sg = idx & 15;
        int o = jt * 64 + sg * 4;
        size_t go = (size_t)(b * T_N + t0 + row) * 256 + o;
        float4 rv = ((const float4*)sr)[row * 17 + sg];
        float4 b1 = *(const float4*)(rb + o);
        if (!last) {
            float4 xv = *(const float4*)(g_x + go);
            float4 v = make_float4(xv.x + rv.x + b1.x, xv.y + rv.y + b1.y,
                                   xv.z + rv.z + b1.z, xv.w + rv.w + b1.w);
            *(float4*)(g_x + go) = v;
            __nv_bfloat16 h0 = __float2bfloat16(v.x), h1 = __float2bfloat16(v.y);
            __nv_bfloat16 h2 = __float2bfloat16(v.z), h3 = __float2bfloat16(v.w);
            __nv_bfloat162 hh0 = {h0, h1}, hh1 = {h2, h3};
            *(__nv_bfloat162*)(g_xh + go) = hh0;
            *(__nv_bfloat162*)(g_xh + go + 2) = hh1;
            __nv_bfloat162 ll0 = {__float2bfloat16(v.x - __bfloat162float(h0)),
                                  __float2bfloat16(v.y - __bfloat162float(h1))};
            __nv_bfloat162 ll1 = {__float2bfloat16(v.z - __bfloat162float(h2)),
                                  __float2bfloat16(v.w - __bfloat162float(h3))};
            *(__nv_bfloat162*)(g_xl + go) = ll0;
            *(__nv_bfloat162*)(g_xl + go + 2) = ll1;
            float4 sv = ((const float4*)ss)[row * 17 + sg];
            float4 b2 = *(const float4*)(rb + 256 + o);
            float4 ov = *(const float4*)(g_oa + go);
            ov.x += sv.x + b2.x; ov.y += sv.y + b2.y;
            ov.z += sv.z + b2.z; ov.w += sv.w + b2.w;
            *(float4*)(g_oa + go) = ov;
        } else {
            float4 ov = *(const float4*)(g_oa + go);
            ov.x += rv.x + b1.x; ov.y += rv.y + b1.y;
            ov.z += rv.z + b1.z; ov.w += rv.w + b1.w;
            *(float4*)(g_oa + go) = ov;
        }
    }
    __syncthreads();
}

// ---------------- persistent scheduler kernel ----------------
__global__ __launch_bounds__(256, 2) void wn_k(const float* __restrict__ ib_,
                                               const float* __restrict__ cb_,
                                               const float* __restrict__ rb_) {
    extern __shared__ char sm[];
    __shared__ int s_item;
    uint32_t sb = smem_u32(sm);

    for (;;) {
        if (threadIdx.x == 0) s_item = atomicAdd(&g_qhead, 1);
        __syncthreads();
        int item = s_item;
        if (item >= TOTAL_ITEMS) return;

        int li = item / ITEMS_PER_LAYER;
        int r  = item % ITEMS_PER_LAYER;
        int is_conv = r < 1024;
        int cid = is_conv ? r : r - 1024;
        int tt = cid >> 5, b = (cid >> 2) & 7, jt = cid & 3;

        // dependency wait (poll with L2 loads; acquire via threadfence)
        if (threadIdx.x == 0) {
            if (is_conv) {
                if (li > 0) {
                    int lo = tt > 0 ? tt - 1 : 0;
                    int hi = tt < NTT - 1 ? tt + 1 : NTT - 1;
                    for (int m = lo; m <= hi; m++)
                        while (ld_cg(&g_rdone[li - 1][b * NTT + m]) < 4)
                            __nanosleep(64);
                }
            } else {
                while (ld_cg(&g_cdone[li][b * NTT + tt]) < 4)
                    __nanosleep(64);
            }
            __threadfence();
        }
        __syncthreads();

        if (is_conv)
            conv_body(sm, sb, li, DILC[li], b, tt * 128, jt, ib_, cb_);
        else
            rs_body(sm, sb, li, b, tt * 128, jt, li == NL - 1, rb_);

        __threadfence();
        __syncthreads();
        if (threadIdx.x == 0) {
            if (is_conv) atomicAdd(&g_cdone[li][b * NTT + tt], 1);
            else         atomicAdd(&g_rdone[li][b * NTT + tt], 1);
        }
    }
}

// ---------------- end conv + affine ----------------
__global__ void end_k(const float* __restrict__ f, const float* __restrict__ ew,
                      const float* __restrict__ eb, float* __restrict__ out) {
    __shared__ float w[2048];
    int tid = threadIdx.x;
    for (int e = tid; e < 2048; e += 256) w[e] = ew[e];
    __syncthreads();
    int idx = blockIdx.x * 256 + tid;
    int t = idx & (T_N - 1), b = idx >> 12;
    float acc[8];
#pragma unroll
    for (int o = 0; o < 8; o++) acc[o] = eb[o];
    const float4* oa = (const float4*)(g_oa + (size_t)(b * T_N + t) * 256);
    for (int c4 = 0; c4 < 64; c4++) {
        float4 v = oa[c4];
#pragma unroll
        for (int o = 0; o < 8; o++) {
            acc[o] = fmaf(v.x, w[o * 256 + c4 * 4],     acc[o]);
            acc[o] = fmaf(v.y, w[o * 256 + c4 * 4 + 1], acc[o]);
            acc[o] = fmaf(v.z, w[o * 256 + c4 * 4 + 2], acc[o]);
            acc[o] = fmaf(v.w, w[o * 256 + c4 * 4 + 3], acc[o]);
        }
    }
    const float* fb = f + (size_t)b * 8 * T_N + t;
    float* cc = out + (size_t)b * 8 * T_N + t;
    float* lo = out + (size_t)B_N * 8 * T_N + (size_t)b * 4 * T_N + t;
#pragma unroll
    for (int l = 0; l < 4; l++) {
        cc[(size_t)l * T_N] = fb[(size_t)l * T_N];
        float ls = acc[4 + l];
        cc[(size_t)(4 + l) * T_N] = expf(ls) * fb[(size_t)(4 + l) * T_N] + acc[l];
        lo[(size_t)l * T_N] = ls;
    }
}

// ---------------- launch ----------------
extern "C" void kernel_launch(void* const* d_in, const int* in_sizes, int n_in,
                              void* d_out, int out_size) {
    const float* forecast = (const float*)d_in[0];
    const float* context  = (const float*)d_in[1];
    const float* start_w  = (const float*)d_in[2];
    const float* start_b  = (const float*)d_in[3];
    const float* cond_w   = (const float*)d_in[4];
    const float* cond_b   = (const float*)d_in[5];
    const float* in_w     = (const float*)d_in[6];
    const float* in_b     = (const float*)d_in[7];
    const float* rs_w     = (const float*)d_in[8];
    const float* rs_b     = (const float*)d_in[9];
    const float* end_w    = (const float*)d_in[10];
    const float* end_b    = (const float*)d_in[11];
    float* out = (float*)d_out;
    (void)in_sizes; (void)n_in; (void)out_size;

    cudaFuncSetAttribute(wn_k, cudaFuncAttributeMaxDynamicSharedMemorySize, GEMM_SMEM);

    zero_sync<<<8, 256>>>();
    prep_all<<<(NL * (NQC + NQR) * 32768 + 255) / 256, 256>>>(in_w, cond_w, rs_w);
    ctx_prep<<<dim3(T_N / 32, B_N), 256>>>(context);
    start_k<<<dim3(T_N / 128, B_N), 256>>>(forecast, start_w, start_b);

    wn_k<<<GRID_P, 256, GEMM_SMEM>>>(in_b, cond_b, rs_b);

    end_k<<<(B_N * T_N) / 256, 256>>>(forecast, end_w, end_b, out);
}

// round 17
// speedup vs baseline: 1.1612x; 1.1612x over previous
#include <cuda_runtime.h>
#include <cuda_bf16.h>
#include <cstdint>

#define T_N 4096
#define B_N 8
#define NL  8
#define NQC 40               // conv K-chunks (36 x-parts + 4 packed ctx)
#define NQR 12               // rs K-chunks
#define NIC 28               // deduped conv images: 3 taps x (4 hi + 4 lo) + 4 ctx
#define NIR 8                // deduped rs images: 4 hi + 4 lo
#define STG_B 32768          // per stage: 16KB A + 16KB B
#define GEMM_SMEM 98304      // 3 stages, 2 CTAs/SM

// ---------------- device scratch ----------------
__device__ __align__(16) float         g_x [B_N*T_N*256];
__device__ __align__(16) __nv_bfloat16 g_xh[B_N*T_N*256];
__device__ __align__(16) __nv_bfloat16 g_xl[B_N*T_N*256];
__device__ __align__(16) __nv_bfloat16 g_ah[B_N*T_N*256];
__device__ __align__(16) __nv_bfloat16 g_al[B_N*T_N*256];
__device__ __align__(16) float         g_oa[B_N*T_N*256];
__device__ __align__(16) __nv_bfloat16 g_ch[B_N*T_N*80];
__device__ __align__(16) __nv_bfloat16 g_cl[B_N*T_N*80];
__device__ __align__(16) __nv_bfloat16 g_wc[(size_t)NL*NIC*32768];
__device__ __align__(16) __nv_bfloat16 g_wr[(size_t)NL*NIR*32768];

// ---------------- helpers ----------------
__device__ __forceinline__ uint32_t smem_u32(const void* p) {
    uint32_t a;
    asm("{ .reg .u64 t; cvta.to.shared.u64 t, %1; cvt.u32.u64 %0, t; }" : "=r"(a) : "l"(p));
    return a;
}
__device__ __forceinline__ uint32_t swz(uint32_t x) { return x ^ ((x >> 3) & 0x70); }

#define CP16(dst, src, sz) \
    asm volatile("cp.async.cg.shared.global [%0], [%1], 16, %2;" \
        :: "r"(dst), "l"(src), "r"(sz) : "memory")
#define CPCOMMIT() asm volatile("cp.async.commit_group;" ::: "memory")
#define CPWAIT1()  asm volatile("cp.async.wait_group 1;" ::: "memory")
#define CPWAIT0()  asm volatile("cp.async.wait_group 0;" ::: "memory")

__device__ __forceinline__ void ldmx4(uint32_t* r, uint32_t a) {
    asm volatile("ldmatrix.sync.aligned.m8n8.x4.shared.b16 {%0,%1,%2,%3}, [%4];"
        : "=r"(r[0]), "=r"(r[1]), "=r"(r[2]), "=r"(r[3]) : "r"(a));
}
__device__ __forceinline__ void mma16816(float* c, const uint32_t* a, const uint32_t* b) {
    asm volatile("mma.sync.aligned.m16n8k16.row.col.f32.bf16.bf16.f32 "
        "{%0,%1,%2,%3}, {%4,%5,%6,%7}, {%8,%9}, {%0,%1,%2,%3};"
        : "+f"(c[0]), "+f"(c[1]), "+f"(c[2]), "+f"(c[3])
        : "r"(a[0]), "r"(a[1]), "r"(a[2]), "r"(a[3]), "r"(b[0]), "r"(b[1]));
}
__device__ __forceinline__ float sigf(float x) { return 1.f / (1.f + __expf(-x)); }

// ---------------- weight-image prep (deduped: hi shared by p=0,1) ----------------
// conv image img<24: tap=img>>3, lohi=(img>>2)&1, c=(img&3)*64+k, value = lohi?lo(w):hi(w)
// img 24..27: packed ctx, sidx=(img-24)*64+k: [0,80) hi(w[m=sidx]); [80,160) hi(w[m=sidx-80]);
//             [160,240) lo(w[m=sidx-160]); else 0.
// rs image: lohi=img>>2, c=(img&3)*64+k.
__global__ void prep_all(const float* __restrict__ in_w,
                         const float* __restrict__ cond_w,
                         const float* __restrict__ rs_w) {
    int idx = blockIdx.x * 256 + threadIdx.x;
    const int NC = NL * NIC * 32768;
    if (idx < NC) {
        int li = idx / (NIC * 32768);
        int r  = idx % (NIC * 32768);
        int img = r >> 15, rr = r & 32767;
        int ng = rr >> 6, k = rr & 63;
        int jt = ng >> 7, nq = ng & 127;
        int o = jt * 64 + (nq >> 1), s = nq & 1;
        int och = o + s * 256;
        float w; int lo;
        if (img < 24) {
            int tap = img >> 3; lo = (img >> 2) & 1;
            int c = (img & 3) * 64 + k;
            w = in_w[((size_t)(li * 512 + och) * 256 + c) * 3 + tap];
        } else {
            int sidx = (img - 24) * 64 + k;
            if (sidx < 80)       { w = cond_w[(size_t)(li * 512 + och) * 80 + sidx];        lo = 0; }
            else if (sidx < 160) { w = cond_w[(size_t)(li * 512 + och) * 80 + sidx - 80];   lo = 0; }
            else if (sidx < 240) { w = cond_w[(size_t)(li * 512 + och) * 80 + sidx - 160];  lo = 1; }
            else                 { w = 0.f; lo = 0; }
        }
        __nv_bfloat16 h = __float2bfloat16(w);
        if (lo) h = __float2bfloat16(w - __bfloat162float(h));
        g_wc[(size_t)(li * NIC + img) * 32768 + jt * 8192 + (swz((uint32_t)nq * 128 + k * 2) >> 1)] = h;
    } else {
        idx -= NC;
        if (idx >= NL * NIR * 32768) return;
        int li = idx / (NIR * 32768);
        int r  = idx % (NIR * 32768);
        int img = r >> 15, rr = r & 32767;
        int ng = rr >> 6, k = rr & 63;
        int jt = ng >> 7, nq = ng & 127;
        int o = jt * 64 + (nq >> 1), s = nq & 1;
        int och = o + s * 256;
        int lo = img >> 2, c = (img & 3) * 64 + k;
        float w = rs_w[(size_t)(li * 512 + och) * 256 + c];
        __nv_bfloat16 h = __float2bfloat16(w);
        if (lo) h = __float2bfloat16(w - __bfloat162float(h));
        g_wr[(size_t)(li * NIR + img) * 32768 + jt * 8192 + (swz((uint32_t)nq * 128 + k * 2) >> 1)] = h;
    }
}

// ---------------- context transpose+split ----------------
__global__ void ctx_prep(const float* __restrict__ ctx) {
    __shared__ float tile[80][33];
    int b = blockIdx.y, t0 = blockIdx.x * 32, tid = threadIdx.x;
    int i = tid & 31, m0 = tid >> 5;
    for (int mm = m0; mm < 80; mm += 8)
        tile[mm][i] = ctx[((size_t)b * 80 + mm) * T_N + t0 + i];
    __syncthreads();
    int tt = tid >> 3, sg = tid & 7;
    size_t rb = ((size_t)b * T_N + t0 + tt) * 80;
    for (int e = 0; e < 10; e++) {
        int m = sg * 10 + e;
        float v = tile[m][tt];
        __nv_bfloat16 h = __float2bfloat16(v);
        g_ch[rb + m] = h;
        g_cl[rb + m] = __float2bfloat16(v - __bfloat162float(h));
    }
}

// ---------------- start conv ----------------
__global__ void start_k(const float* __restrict__ f, const float* __restrict__ sw,
                        const float* __restrict__ sb) {
    __shared__ float ft[4][128];
    int t0 = blockIdx.x * 128, b = blockIdx.y, c = threadIdx.x;
    for (int e = 0; e < 2; e++) {
        int idx = e * 256 + c;
        ft[idx >> 7][idx & 127] = f[((size_t)b * 8 + (idx >> 7)) * T_N + t0 + (idx & 127)];
    }
    float w0 = sw[c * 4], w1 = sw[c * 4 + 1], w2 = sw[c * 4 + 2], w3 = sw[c * 4 + 3];
    float bb = sb[c];
    __syncthreads();
    for (int t = 0; t < 128; t++) {
        float v = fmaf(ft[3][t], w3, fmaf(ft[2][t], w2, fmaf(ft[1][t], w1, fmaf(ft[0][t], w0, bb))));
        size_t o = ((size_t)b * T_N + t0 + t) * 256 + c;
        g_x[o] = v; g_oa[o] = 0.f;
        __nv_bfloat16 h = __float2bfloat16(v);
        g_xh[o] = h;
        g_xl[o] = __float2bfloat16(v - __bfloat162float(h));
    }
}

// ---------------- conv GEMM + gate (128t x 128n per CTA, 2 CTAs/SM) ----------------
__global__ __launch_bounds__(256, 2) void conv_k(const float* __restrict__ ib_,
                                                 const float* __restrict__ cb_,
                                                 int li, int d) {
    extern __shared__ char sm[];
    uint32_t sb = smem_u32(sm);
    int tid = threadIdx.x, wid = tid >> 5, lane = tid & 31;
    int t0 = blockIdx.x * 128, jt = blockIdx.y, b = blockIdx.z;

    int row0 = tid >> 3, seg = tid & 7;
    uint32_t adst0  = (uint32_t)row0 * 128 + (((uint32_t)seg * 16) ^ (((uint32_t)row0 & 7) << 4));
    uint32_t abase0 = ((uint32_t)(b * T_N + t0 + row0)) * 512 + (uint32_t)seg * 16;
    uint32_t crow0  = ((uint32_t)(b * T_N + t0 + row0)) * 160;

    auto stageA = [&](int q, int st) {
        uint32_t ad = sb + st * STG_B + adst0;
        if (q < 36) {
            int pp = q >> 2, p = pp % 3, tap = pp / 3, c0 = (q & 3) * 64;
            const char* bp = (const char*)((p == 1) ? g_xl : g_xh);
            int tsh = (tap - 1) * d;
            const char* base = bp + abase0 + (long long)tsh * 512 + c0 * 2;
#pragma unroll
            for (int e = 0; e < 4; e++) {
                int t = t0 + row0 + 32 * e + tsh;
                int sz = (t >= 0 && t < T_N) ? 16 : 0;
                const char* src = sz ? (base + e * 16384) : bp;
                CP16(ad + e * 4096, src, sz);
            }
        } else {
            int s0 = (q - 36) * 64 + seg * 8;
            const char* base; int sz = 16;
            if (s0 < 80)       base = (const char*)g_ch + crow0 + s0 * 2;
            else if (s0 < 160) base = (const char*)g_cl + crow0 + (s0 - 80) * 2;
            else if (s0 < 240) base = (const char*)g_ch + crow0 + (s0 - 160) * 2;
            else             { base = (const char*)g_ch; sz = 0; }
#pragma unroll
            for (int e = 0; e < 4; e++)
                CP16(ad + e * 4096, base + (sz ? e * 5120 : 0), sz);
        }
    };
    auto stageB = [&](int q, int st) {
        int img;
        if (q < 36) {
            int pp = q >> 2, tap = pp / 3, p = pp % 3;
            img = tap * 8 + (p == 2 ? 4 : 0) + (q & 3);
        } else {
            img = q - 12;   // 36..39 -> 24..27
        }
        const char* bsrc = (const char*)(g_wc + (size_t)(li * NIC + img) * 32768 + jt * 8192) + tid * 16;
        uint32_t bd = sb + st * STG_B + 16384 + tid * 16;
#pragma unroll
        for (int e = 0; e < 4; e++)
            CP16(bd + e * 4096, bsrc + e * 4096, 16);
    };

    float c[2][8][4];
#pragma unroll
    for (int i = 0; i < 2; i++)
#pragma unroll
        for (int j = 0; j < 8; j++)
#pragma unroll
            for (int k = 0; k < 4; k++) c[i][j][k] = 0.f;

    int mb = (wid & 3) * 32, nb = (wid >> 2) * 64;
    int rA = lane & 15, cA = (lane >> 4) * 16;
    int rB = ((lane >> 4) & 1) * 8 + (lane & 7), cB = ((lane >> 3) & 1) * 16;

    uint32_t aRow = (uint32_t)(mb + rA) * 128;
    uint32_t bRow = (uint32_t)(nb + rB) * 128;
    uint32_t axr = ((uint32_t)rA & 7) << 4;
    uint32_t bxr = ((uint32_t)rB & 7) << 4;
    uint32_t kxA[4], kxB[4];
#pragma unroll
    for (int ks = 0; ks < 4; ks++) {
        kxA[ks] = ((uint32_t)(ks * 32 + cA)) ^ axr;
        kxB[ks] = ((uint32_t)(ks * 32 + cB)) ^ bxr;
    }

    stageA(0, 0); stageB(0, 0); CPCOMMIT();
    stageA(1, 1); stageB(1, 1); CPCOMMIT();

    for (int q = 0; q < NQC; q++) {
        int st = q % 3;
        if (q == NQC - 1) CPWAIT0(); else CPWAIT1();
        __syncthreads();
        if (q + 2 < NQC) {
            int st2 = (q + 2) % 3;
            stageA(q + 2, st2); stageB(q + 2, st2); CPCOMMIT();
        }
        uint32_t aB = sb + st * STG_B, bB = aB + 16384;
        uint32_t aA0 = aB + aRow, aA1 = aA0 + 2048;
        uint32_t bBr = bB + bRow;

        uint32_t af[2][2][4], bf[2][4];
        ldmx4(af[0][0], aA0 + kxA[0]);
        ldmx4(af[0][1], aA1 + kxA[0]);
        ldmx4(bf[0], bBr + kxB[0]);
#pragma unroll
        for (int ks = 0; ks < 4; ks++) {
            int cs = ks & 1, ns = cs ^ 1;
            if (ks < 3) {
                ldmx4(af[ns][0], aA0 + kxA[ks + 1]);
                ldmx4(af[ns][1], aA1 + kxA[ks + 1]);
            }
#pragma unroll
            for (int nj = 0; nj < 4; nj++) {
                int cb2 = nj & 1, nb2 = cb2 ^ 1;
                if (nj < 3)      ldmx4(bf[nb2], bBr + (nj + 1) * 2048 + kxB[ks]);
                else if (ks < 3) ldmx4(bf[nb2], bBr + kxB[ks + 1]);
                mma16816(c[0][nj * 2],     af[cs][0], &bf[cb2][0]);
                mma16816(c[0][nj * 2 + 1], af[cs][0], &bf[cb2][2]);
                mma16816(c[1][nj * 2],     af[cs][1], &bf[cb2][0]);
                mma16816(c[1][nj * 2 + 1], af[cs][1], &bf[cb2][2]);
            }
        }
    }
    __syncthreads();

    // epilogue: gate -> smem tiles (pitch 72 bf16) -> coalesced global
    __nv_bfloat16* shh = (__nv_bfloat16*)sm;
    __nv_bfloat16* sll = (__nv_bfloat16*)(sm + 20480);
    const float* ib = ib_ + li * 512;
    const float* cb = cb_ + li * 512;
    int qrow = lane >> 2, qcol = lane & 3;
#pragma unroll
    for (int nt = 0; nt < 8; nt++) {
        int ol = (nb >> 1) + nt * 4 + qcol;
        int o = jt * 64 + ol;
        float b1 = ib[o] + cb[o];
        float b2 = ib[o + 256] + cb[o + 256];
#pragma unroll
        for (int mi = 0; mi < 2; mi++) {
            int tl = mb + mi * 16 + qrow;
            float a0 = tanhf(c[mi][nt][0] + b1) * sigf(c[mi][nt][1] + b2);
            float a1 = tanhf(c[mi][nt][2] + b1) * sigf(c[mi][nt][3] + b2);
            __nv_bfloat16 h0 = __float2bfloat16(a0);
            __nv_bfloat16 h1 = __float2bfloat16(a1);
            shh[tl * 72 + ol] = h0;
            sll[tl * 72 + ol] = __float2bfloat16(a0 - __bfloat162float(h0));
            shh[(tl + 8) * 72 + ol] = h1;
            sll[(tl + 8) * 72 + ol] = __float2bfloat16(a1 - __bfloat162float(h1));
        }
    }
    __syncthreads();
#pragma unroll
    for (int e = 0; e < 4; e++) {
        int idx = e * 256 + tid;
        int row = idx >> 3, sg = idx & 7;
        size_t go = (size_t)(b * T_N + t0 + row) * 256 + jt * 64;
        ((uint4*)(g_ah + go))[sg] = ((const uint4*)shh)[row * 9 + sg];
        ((uint4*)(g_al + go))[sg] = ((const uint4*)sll)[row * 9 + sg];
    }
}

// ---------------- rs GEMM + residual/skip ----------------
__global__ __launch_bounds__(256, 2) void rs_k(const float* __restrict__ rb_,
                                               int li, int last) {
    extern __shared__ char sm[];
    uint32_t sb = smem_u32(sm);
    int tid = threadIdx.x, wid = tid >> 5, lane = tid & 31;
    int t0 = blockIdx.x * 128, jt = blockIdx.y, b = blockIdx.z;

    int row0 = tid >> 3, seg = tid & 7;
    uint32_t adst0  = (uint32_t)row0 * 128 + (((uint32_t)seg * 16) ^ (((uint32_t)row0 & 7) << 4));
    uint32_t abase0 = ((uint32_t)(b * T_N + t0 + row0)) * 512 + (uint32_t)seg * 16;

    auto stageA = [&](int q, int st) {
        int p = q >> 2, c0 = (q & 3) * 64;
        const char* base = (const char*)((p == 1) ? g_al : g_ah) + abase0 + c0 * 2;
        uint32_t ad = sb + st * STG_B + adst0;
#pragma unroll
        for (int e = 0; e < 4; e++)
            CP16(ad + e * 4096, base + e * 16384, 16);
    };
    auto stageB = [&](int q, int st) {
        int p = q >> 2;
        int img = (p == 2 ? 4 : 0) + (q & 3);
        const char* bsrc = (const char*)(g_wr + (size_t)(li * NIR + img) * 32768 + jt * 8192) + tid * 16;
        uint32_t bd = sb + st * STG_B + 16384 + tid * 16;
#pragma unroll
        for (int e = 0; e < 4; e++)
            CP16(bd + e * 4096, bsrc + e * 4096, 16);
    };

    float c[2][8][4];
#pragma unroll
    for (int i = 0; i < 2; i++)
#pragma unroll
        for (int j = 0; j < 8; j++)
#pragma unroll
            for (int k = 0; k < 4; k++) c[i][j][k] = 0.f;

    int mb = (wid & 3) * 32, nb = (wid >> 2) * 64;
    int rA = lane & 15, cA = (lane >> 4) * 16;
    int rB = ((lane >> 4) & 1) * 8 + (lane & 7), cB = ((lane >> 3) & 1) * 16;

    uint32_t aRow = (uint32_t)(mb + rA) * 128;
    uint32_t bRow = (uint32_t)(nb + rB) * 128;
    uint32_t axr = ((uint32_t)rA & 7) << 4;
    uint32_t bxr = ((uint32_t)rB & 7) << 4;
    uint32_t kxA[4], kxB[4];
#pragma unroll
    for (int ks = 0; ks < 4; ks++) {
        kxA[ks] = ((uint32_t)(ks * 32 + cA)) ^ axr;
        kxB[ks] = ((uint32_t)(ks * 32 + cB)) ^ bxr;
    }

    stageA(0, 0); stageB(0, 0); CPCOMMIT();
    stageA(1, 1); stageB(1, 1); CPCOMMIT();

    for (int q = 0; q < NQR; q++) {
        int st = q % 3;
        if (q == NQR - 1) CPWAIT0(); else CPWAIT1();
        __syncthreads();
        if (q + 2 < NQR) {
            int st2 = (q + 2) % 3;
            stageA(q + 2, st2); stageB(q + 2, st2); CPCOMMIT();
        }
        uint32_t aB = sb + st * STG_B, bB = aB + 16384;
        uint32_t aA0 = aB + aRow, aA1 = aA0 + 2048;
        uint32_t bBr = bB + bRow;

        uint32_t af[2][2][4], bf[2][4];
        ldmx4(af[0][0], aA0 + kxA[0]);
        ldmx4(af[0][1], aA1 + kxA[0]);
        ldmx4(bf[0], bBr + kxB[0]);
#pragma unroll
        for (int ks = 0; ks < 4; ks++) {
            int cs = ks & 1, ns = cs ^ 1;
            if (ks < 3) {
                ldmx4(af[ns][0], aA0 + kxA[ks + 1]);
                ldmx4(af[ns][1], aA1 + kxA[ks + 1]);
            }
#pragma unroll
            for (int nj = 0; nj < 4; nj++) {
                int cb2 = nj & 1, nb2 = cb2 ^ 1;
                if (nj < 3)      ldmx4(bf[nb2], bBr + (nj + 1) * 2048 + kxB[ks]);
                else if (ks < 3) ldmx4(bf[nb2], bBr + kxB[ks + 1]);
                mma16816(c[0][nj * 2],     af[cs][0], &bf[cb2][0]);
                mma16816(c[0][nj * 2 + 1], af[cs][0], &bf[cb2][2]);
                mma16816(c[1][nj * 2],     af[cs][1], &bf[cb2][0]);
                mma16816(c[1][nj * 2 + 1], af[cs][1], &bf[cb2][2]);
            }
        }
    }
    __syncthreads();

    // epilogue via smem tiles (fp32, pitch 68)
    float* sr = (float*)sm;
    float* ss = (float*)(sm + 34816);
    int qrow = lane >> 2, qcol = lane & 3;
#pragma unroll
    for (int nt = 0; nt < 8; nt++) {
        int ol = (nb >> 1) + nt * 4 + qcol;
#pragma unroll
        for (int mi = 0; mi < 2; mi++) {
            int tl = mb + mi * 16 + qrow;
            sr[tl * 68 + ol] = c[mi][nt][0];
            ss[tl * 68 + ol] = c[mi][nt][1];
            sr[(tl + 8) * 68 + ol] = c[mi][nt][2];
            ss[(tl + 8) * 68 + ol] = c[mi][nt][3];
        }
    }
    __syncthreads();
    const float* rb = rb_ + li * 512;
#pragma unroll
    for (int e = 0; e < 8; e++) {
        int idx = e * 256 + tid;
        int row = idx >> 4, sg = idx & 15;
        int o = jt * 64 + sg * 4;
        size_t go = (size_t)(b * T_N + t0 + row) * 256 + o;
        float4 rv = ((const float4*)sr)[row * 17 + sg];
        float4 b1 = *(const float4*)(rb + o);
        if (!last) {
            float4 xv = *(const float4*)(g_x + go);
            float4 v = make_float4(xv.x + rv.x + b1.x, xv.y + rv.y + b1.y,
                                   xv.z + rv.z + b1.z, xv.w + rv.w + b1.w);
            *(float4*)(g_x + go) = v;
            __nv_bfloat16 h0 = __float2bfloat16(v.x), h1 = __float2bfloat16(v.y);
            __nv_bfloat16 h2 = __float2bfloat16(v.z), h3 = __float2bfloat16(v.w);
            __nv_bfloat162 hh0 = {h0, h1}, hh1 = {h2, h3};
            *(__nv_bfloat162*)(g_xh + go) = hh0;
            *(__nv_bfloat162*)(g_xh + go + 2) = hh1;
            __nv_bfloat162 ll0 = {__float2bfloat16(v.x - __bfloat162float(h0)),
                                  __float2bfloat16(v.y - __bfloat162float(h1))};
            __nv_bfloat162 ll1 = {__float2bfloat16(v.z - __bfloat162float(h2)),
                                  __float2bfloat16(v.w - __bfloat162float(h3))};
            *(__nv_bfloat162*)(g_xl + go) = ll0;
            *(__nv_bfloat162*)(g_xl + go + 2) = ll1;
            float4 sv = ((const float4*)ss)[row * 17 + sg];
            float4 b2 = *(const float4*)(rb + 256 + o);
            float4 ov = *(const float4*)(g_oa + go);
            ov.x += sv.x + b2.x; ov.y += sv.y + b2.y;
            ov.z += sv.z + b2.z; ov.w += sv.w + b2.w;
            *(float4*)(g_oa + go) = ov;
        } else {
            float4 ov = *(const float4*)(g_oa + go);
            ov.x += rv.x + b1.x; ov.y += rv.y + b1.y;
            ov.z += rv.z + b1.z; ov.w += rv.w + b1.w;
            *(float4*)(g_oa + go) = ov;
        }
    }
}

// ---------------- end conv + affine ----------------
__global__ void end_k(const float* __restrict__ f, const float* __restrict__ ew,
                      const float* __restrict__ eb, float* __restrict__ out) {
    __shared__ float w[2048];
    int tid = threadIdx.x;
    for (int e = tid; e < 2048; e += 256) w[e] = ew[e];
    __syncthreads();
    int idx = blockIdx.x * 256 + tid;
    int t = idx & (T_N - 1), b = idx >> 12;
    float acc[8];
#pragma unroll
    for (int o = 0; o < 8; o++) acc[o] = eb[o];
    const float4* oa = (const float4*)(g_oa + (size_t)(b * T_N + t) * 256);
    for (int c4 = 0; c4 < 64; c4++) {
        float4 v = oa[c4];
#pragma unroll
        for (int o = 0; o < 8; o++) {
            acc[o] = fmaf(v.x, w[o * 256 + c4 * 4],     acc[o]);
            acc[o] = fmaf(v.y, w[o * 256 + c4 * 4 + 1], acc[o]);
            acc[o] = fmaf(v.z, w[o * 256 + c4 * 4 + 2], acc[o]);
            acc[o] = fmaf(v.w, w[o * 256 + c4 * 4 + 3], acc[o]);
        }
    }
    const float* fb = f + (size_t)b * 8 * T_N + t;
    float* cc = out + (size_t)b * 8 * T_N + t;
    float* lo = out + (size_t)B_N * 8 * T_N + (size_t)b * 4 * T_N + t;
#pragma unroll
    for (int l = 0; l < 4; l++) {
        cc[(size_t)l * T_N] = fb[(size_t)l * T_N];
        float ls = acc[4 + l];
        cc[(size_t)(4 + l) * T_N] = expf(ls) * fb[(size_t)(4 + l) * T_N] + acc[l];
        lo[(size_t)l * T_N] = ls;
    }
}

// ---------------- launch ----------------
static const int DIL[NL] = {1, 2, 4, 8, 16, 32, 64, 128};

extern "C" void kernel_launch(void* const* d_in, const int* in_sizes, int n_in,
                              void* d_out, int out_size) {
    const float* forecast = (const float*)d_in[0];
    const float* context  = (const float*)d_in[1];
    const float* start_w  = (const float*)d_in[2];
    const float* start_b  = (const float*)d_in[3];
    const float* cond_w   = (const float*)d_in[4];
    const float* cond_b   = (const float*)d_in[5];
    const float* in_w     = (const float*)d_in[6];
    const float* in_b     = (const float*)d_in[7];
    const float* rs_w     = (const float*)d_in[8];
    const float* rs_b     = (const float*)d_in[9];
    const float* end_w    = (const float*)d_in[10];
    const float* end_b    = (const float*)d_in[11];
    float* out = (float*)d_out;
    (void)in_sizes; (void)n_in; (void)out_size;

    cudaFuncSetAttribute(conv_k, cudaFuncAttributeMaxDynamicSharedMemorySize, GEMM_SMEM);
    cudaFuncSetAttribute(rs_k,   cudaFuncAttributeMaxDynamicSharedMemorySize, GEMM_SMEM);

    prep_all<<<(NL * (NIC + NIR) * 32768 + 255) / 256, 256>>>(in_w, cond_w, rs_w);
    ctx_prep<<<dim3(T_N / 32, B_N), 256>>>(context);
    start_k<<<dim3(T_N / 128, B_N), 256>>>(forecast, start_w, start_b);

    dim3 grid(T_N / 128, 4, B_N);
    for (int li = 0; li < NL; li++) {
        conv_k<<<grid, 256, GEMM_SMEM>>>(in_b, cond_b, li, DIL[li]);
        rs_k<<<grid, 256, GEMM_SMEM>>>(rs_b, li, li == NL - 1 ? 1 : 0);
    }
    end_k<<<(B_N * T_N) / 256, 256>>>(forecast, end_w, end_b, out);
}